// round 4
// baseline (speedup 1.0000x reference)
#include <cuda_runtime.h>
#include <cstdint>

#define B_   128
#define S_   128
#define I_   300
#define H_   1024
#define G4_  4096
#define CC_  2

#define WSTRIDE 1040            // words per W smem row (1024 + 16 pad; 1040 % 32 == 16)
#define ASTRIDE 80              // words per A-stage smem row (64 + 16 pad; 80 % 32 == 16)
#define SMEM_WORDS (32 * WSTRIDE + 2 * 128 * ASTRIDE)
#define SMEM_BYTES (SMEM_WORDS * 4)   // 215040

// ---------------- static scratch ----------------
__device__ float d_G[(size_t)S_ * B_ * G4_];        // [s][b][4096] input-path preacts (+biases)
__device__ float d_hs[(size_t)(S_ + 1) * B_ * H_];  // h per step, k-interleaved layout; slot 0 = 0
__device__ int   d_ctr;                             // grid barrier counter

// ---------------- helpers ----------------
__device__ __forceinline__ uint32_t f2tf(float x) {
    uint32_t u;
    asm("cvt.rna.tf32.f32 %0, %1;" : "=r"(u) : "f"(x));
    return u;
}

__device__ __forceinline__ void mma_tf32(float c[4], const uint32_t a[4], const uint32_t b[2]) {
    asm volatile(
        "mma.sync.aligned.m16n8k8.row.col.f32.tf32.tf32.f32 "
        "{%0,%1,%2,%3}, {%4,%5,%6,%7}, {%8,%9}, {%0,%1,%2,%3};\n"
        : "+f"(c[0]), "+f"(c[1]), "+f"(c[2]), "+f"(c[3])
        : "r"(a[0]), "r"(a[1]), "r"(a[2]), "r"(a[3]),
          "r"(b[0]), "r"(b[1]));
}

__device__ __forceinline__ float sigf(float x) { return 1.0f / (1.0f + __expf(-x)); }
// safe tanh: no inf/inf NaN at either extreme
__device__ __forceinline__ float tanhf_(float x) { return 2.0f / (1.0f + __expf(-2.0f * x)) - 1.0f; }

// swap bit pairs [1:0] <-> [3:2] within each 16-word block (involution)
__host__ __device__ __forceinline__ int perm16(int k) {
    return (k & ~15) | ((k & 3) << 2) | ((k >> 2) & 3);
}
// smem bank swizzle: word index within row -> physical word (xor by multiples of 4)
__device__ __forceinline__ int swz(int w, int row) {
    return w ^ ((row & 7) << 2) ^ (((w >> 5) & 1) << 2);
}

__device__ __forceinline__ void bar_arrive() {
    asm volatile("red.release.gpu.global.add.s32 [%0], 1;" :: "l"(&d_ctr) : "memory");
}
__device__ __forceinline__ int bar_poll() {
    int v;
    asm volatile("ld.acquire.gpu.global.b32 %0, [%1];" : "=r"(v) : "l"(&d_ctr) : "memory");
    return v;
}

// ---------------- init ----------------
__global__ void init_state() {
    int idx = blockIdx.x * 256 + threadIdx.x;
    if (idx < B_ * H_) d_hs[idx] = 0.0f;     // slot 0 = h0 = 0
    if (idx == 0) d_ctr = 0;
}

// ---------------- input-path GEMM (unchanged from passing R2 kernel) ----------------
__global__ __launch_bounds__(256) void embed_gemm(
    const int* __restrict__ x, const float* __restrict__ embW,
    const float* __restrict__ W_ih, const float* __restrict__ b_ih,
    const float* __restrict__ b_hh)
{
    __shared__ uint32_t As[128][20];
    __shared__ uint32_t Bs[64][20];
    __shared__ int toks[128];

    const int tid = threadIdx.x;
    const int s   = blockIdx.x;
    const int n0  = blockIdx.y * 64;

    if (tid < 128) toks[tid] = x[tid * S_ + s];

    const int w  = tid >> 5, lane = tid & 31;
    const int wm = w >> 1,   wn   = w & 1;
    const int gr = lane >> 2, gc  = lane & 3;
    const int mw = wm * 32,  nw   = wn * 32;

    const int arow = tid >> 1, akb = (tid & 1) * 8;
    const int brow = tid >> 2, bkb = (tid & 3) * 4;

    float acc[2][4][4];
#pragma unroll
    for (int mi = 0; mi < 2; mi++)
#pragma unroll
        for (int ni = 0; ni < 4; ni++)
#pragma unroll
            for (int q = 0; q < 4; q++) acc[mi][ni][q] = 0.0f;

    __syncthreads();

    for (int kt = 0; kt < 19; kt++) {
        const int k0 = kt * 16;
        {
            const float* er = embW + (size_t)toks[arow] * I_;
#pragma unroll
            for (int kk = 0; kk < 8; kk++) {
                int k = k0 + akb + kk;
                As[arow][akb + kk] = f2tf((k < I_) ? er[k] : 0.0f);
            }
        }
        {
            const float* wr = W_ih + (size_t)(n0 + brow) * I_;
#pragma unroll
            for (int kk = 0; kk < 4; kk++) {
                int k = k0 + bkb + kk;
                Bs[brow][bkb + kk] = f2tf((k < I_) ? wr[k] : 0.0f);
            }
        }
        __syncthreads();

#pragma unroll
        for (int ks = 0; ks < 2; ks++) {
            uint32_t a[2][4], b[4][2];
#pragma unroll
            for (int mi = 0; mi < 2; mi++) {
                a[mi][0] = As[mw + mi * 16 + gr][ks * 8 + gc];
                a[mi][1] = As[mw + mi * 16 + 8 + gr][ks * 8 + gc];
                a[mi][2] = As[mw + mi * 16 + gr][ks * 8 + 4 + gc];
                a[mi][3] = As[mw + mi * 16 + 8 + gr][ks * 8 + 4 + gc];
            }
#pragma unroll
            for (int ni = 0; ni < 4; ni++) {
                b[ni][0] = Bs[nw + ni * 8 + gr][ks * 8 + gc];
                b[ni][1] = Bs[nw + ni * 8 + gr][ks * 8 + 4 + gc];
            }
#pragma unroll
            for (int mi = 0; mi < 2; mi++)
#pragma unroll
                for (int ni = 0; ni < 4; ni++)
                    mma_tf32(acc[mi][ni], a[mi], b[ni]);
        }
        __syncthreads();
    }

#pragma unroll
    for (int mi = 0; mi < 2; mi++) {
        const int m0 = mw + mi * 16 + gr;
#pragma unroll
        for (int ni = 0; ni < 4; ni++) {
            const int n = n0 + nw + ni * 8 + gc * 2;
            const float bias0 = b_ih[n] + b_hh[n];
            const float bias1 = b_ih[n + 1] + b_hh[n + 1];
            size_t base0 = ((size_t)s * B_ + m0) * G4_ + n;
            size_t base1 = ((size_t)s * B_ + m0 + 8) * G4_ + n;
            d_G[base0]     = acc[mi][ni][0] + bias0;
            d_G[base0 + 1] = acc[mi][ni][1] + bias1;
            d_G[base1]     = acc[mi][ni][2] + bias0;
            d_G[base1 + 1] = acc[mi][ni][3] + bias1;
        }
    }
}

// ---------------- persistent recurrence: 128 CTAs, all 128 steps ----------------
extern __shared__ float smem_dyn[];

__device__ __forceinline__ void stage_chunk(float* As_buf, const float* hslot,
                                            int chunk, int srow, int shalf)
{
    const float* src = hslot + (size_t)srow * H_ + chunk * 64 + shalf * 32;
    float* dst = As_buf + srow * ASTRIDE;
#pragma unroll
    for (int q = 0; q < 8; q++) {
        float4 v = *reinterpret_cast<const float4*>(src + q * 4);
        int wloc = shalf * 32 + q * 4;
        *reinterpret_cast<float4*>(dst + swz(wloc, srow)) = v;
    }
}

__global__ void __launch_bounds__(256, 1) lstm_persistent(const float* __restrict__ W_hh)
{
    float* Ws = smem_dyn;                   // [32][WSTRIDE] tf32 bits
    float* Ast = smem_dyn + 32 * WSTRIDE;   // [2][128][ASTRIDE]

    const int tid = threadIdx.x;
    const int bid = blockIdx.x;
    const int c0  = bid * 8;

    const int w  = tid >> 5, lane = tid & 31;
    const int gr = lane >> 2, gc = lane & 3;
    const int mw = (w >> 1) * 32;           // 4 m-warps
    const int nw = (w & 1) * 16;            // 2 n-warps

    const int srow = tid >> 1, shalf = tid & 1;

    // ---- preload W slice: smem row p <-> global gate row (gate,jloc) ----
    for (int i = tid; i < 32 * H_; i += 256) {
        int p = i >> 10, k = i & 1023;
        int gate = ((p >> 3) & 1) * 2 + (p & 1);
        int jloc = ((p >> 4) & 1) * 4 + ((p >> 1) & 3);
        float v = W_hh[(size_t)(gate * H_ + c0 + jloc) * H_ + k];
        int wp = perm16(k);
        Ws[p * WSTRIDE + swz(wp, p)] = __uint_as_float(f2tf(v));
    }
    __syncthreads();

    const int jloc_t = (w & 1) * 4 + gc;       // this thread's hidden column (local)
    const int jglob  = c0 + jloc_t;
    const int pglob  = perm16(jglob);          // storage position in interleaved h

    float cReg[4] = {0.0f, 0.0f, 0.0f, 0.0f};

    for (int t = 0; t < S_; t++) {
        const float* hslot = d_hs + (size_t)t * (B_ * H_);

        // stage chunk 0
        stage_chunk(Ast, hslot, 0, srow, shalf);

        // prefetch this thread's 16 G values (in flight during the k-loop)
        float gv[2][2][4];
        {
            const float* Gt = d_G + (size_t)t * B_ * G4_;
#pragma unroll
            for (int mi = 0; mi < 2; mi++)
#pragma unroll
                for (int rs = 0; rs < 2; rs++) {
                    int r = mw + mi * 16 + gr + rs * 8;
                    const float* Gr = Gt + (size_t)r * G4_ + jglob;
#pragma unroll
                    for (int g = 0; g < 4; g++) gv[mi][rs][g] = Gr[g * H_];
                }
        }

        float acc[2][2][4];
#pragma unroll
        for (int mi = 0; mi < 2; mi++)
#pragma unroll
            for (int ni = 0; ni < 2; ni++)
#pragma unroll
                for (int q = 0; q < 4; q++) acc[mi][ni][q] = 0.0f;

        __syncthreads();

        for (int c = 0; c < 16; c++) {
            if (c < 15)
                stage_chunk(Ast + ((c + 1) & 1) * (128 * ASTRIDE), hslot, c + 1, srow, shalf);

            const float* Ab = Ast + (c & 1) * (128 * ASTRIDE);
#pragma unroll
            for (int gl = 0; gl < 4; gl++) {
                const int wbase = gl * 16 + gc * 4;
                uint4 av[2][2], bv[2];
#pragma unroll
                for (int mi = 0; mi < 2; mi++) {
                    const int R0 = mw + mi * 16 + gr;
                    av[mi][0] = *reinterpret_cast<const uint4*>(Ab + R0 * ASTRIDE + swz(wbase, R0));
                    av[mi][1] = *reinterpret_cast<const uint4*>(Ab + (R0 + 8) * ASTRIDE + swz(wbase, R0 + 8));
                }
                const int wfull = (c * 4 + gl) * 16 + gc * 4;
#pragma unroll
                for (int ni = 0; ni < 2; ni++) {
                    const int nb = nw + ni * 8 + gr;
                    bv[ni] = *reinterpret_cast<const uint4*>(Ws + nb * WSTRIDE + swz(wfull, nb));
                }
                // k-chunk 0: words .x (k=gc), .y (k=4+gc)
                {
                    uint32_t b0[2] = {bv[0].x, bv[0].y};
                    uint32_t b1[2] = {bv[1].x, bv[1].y};
#pragma unroll
                    for (int mi = 0; mi < 2; mi++) {
                        uint32_t a[4] = {av[mi][0].x, av[mi][1].x, av[mi][0].y, av[mi][1].y};
                        mma_tf32(acc[mi][0], a, b0);
                        mma_tf32(acc[mi][1], a, b1);
                    }
                }
                // k-chunk 1: words .z (k=8+gc), .w (k=12+gc)
                {
                    uint32_t b0[2] = {bv[0].z, bv[0].w};
                    uint32_t b1[2] = {bv[1].z, bv[1].w};
#pragma unroll
                    for (int mi = 0; mi < 2; mi++) {
                        uint32_t a[4] = {av[mi][0].z, av[mi][1].z, av[mi][0].w, av[mi][1].w};
                        mma_tf32(acc[mi][0], a, b0);
                        mma_tf32(acc[mi][1], a, b1);
                    }
                }
            }
            __syncthreads();
        }

        // ---- epilogue: add G, LSTM cell (c in regs), write h ----
        float* hout = d_hs + (size_t)(t + 1) * (B_ * H_);
#pragma unroll
        for (int mi = 0; mi < 2; mi++)
#pragma unroll
            for (int rs = 0; rs < 2; rs++) {
                const int r = mw + mi * 16 + gr + rs * 8;
                const float ig = acc[mi][0][rs * 2]     + gv[mi][rs][0];
                const float fg = acc[mi][0][rs * 2 + 1] + gv[mi][rs][1];
                const float gg = acc[mi][1][rs * 2]     + gv[mi][rs][2];
                const float og = acc[mi][1][rs * 2 + 1] + gv[mi][rs][3];
                const int ci = mi * 2 + rs;
                const float cn = sigf(fg) * cReg[ci] + sigf(ig) * tanhf_(gg);
                cReg[ci] = cn;
                const float h = sigf(og) * tanhf_(cn);
                hout[(size_t)r * H_ + pglob] = __uint_as_float(f2tf(h));
            }

        // ---- grid barrier ----
        __syncthreads();
        if (tid == 0) {
            bar_arrive();
            const int tgt = 128 * (t + 1);
            while (bar_poll() < tgt) { __nanosleep(40); }
        }
        __syncthreads();
    }
}

// ---------------- output projection + length mask ----------------
__global__ __launch_bounds__(256) void out_proj(
    const int* __restrict__ lengths, const float* __restrict__ linW,
    const float* __restrict__ linb, float* __restrict__ out)
{
    const int gw   = (blockIdx.x * 256 + threadIdx.x) >> 5;
    const int lane = threadIdx.x & 31;
    const int b = gw >> 7;
    const int s = gw & 127;

    const float* __restrict__ h = d_hs + ((size_t)(s + 1) * B_ + b) * H_;
    float s0 = 0.0f, s1 = 0.0f;
#pragma unroll 8
    for (int p = lane; p < H_; p += 32) {
        const int k = perm16(p);              // stored position p holds hidden index perm16(p)
        const float hv = h[p];
        s0 += hv * linW[k];
        s1 += hv * linW[H_ + k];
    }
#pragma unroll
    for (int o = 16; o > 0; o >>= 1) {
        s0 += __shfl_xor_sync(0xFFFFFFFFu, s0, o);
        s1 += __shfl_xor_sync(0xFFFFFFFFu, s1, o);
    }
    if (lane == 0) {
        float* orow = out + ((size_t)b * S_ + s) * CC_;
        if (s < lengths[b]) {
            orow[0] = s0 + linb[0];
            orow[1] = s1 + linb[1];
        } else {
            orow[0] = 1.0f;
            orow[1] = 0.0f;
        }
    }
}

// ---------------- launch ----------------
extern "C" void kernel_launch(void* const* d_in, const int* in_sizes, int n_in,
                              void* d_out, int out_size) {
    const int*   x       = (const int*)d_in[0];
    const int*   lengths = (const int*)d_in[1];
    const float* embW    = (const float*)d_in[2];
    const float* W_ih    = (const float*)d_in[3];
    const float* W_hh    = (const float*)d_in[4];
    const float* b_ih    = (const float*)d_in[5];
    const float* b_hh    = (const float*)d_in[6];
    const float* linW    = (const float*)d_in[7];
    const float* linb    = (const float*)d_in[8];
    float*       out     = (float*)d_out;

    static bool attr_done = false;
    if (!attr_done) {
        cudaFuncSetAttribute(lstm_persistent,
                             cudaFuncAttributeMaxDynamicSharedMemorySize, SMEM_BYTES);
        attr_done = true;
    }

    init_state<<<512, 256>>>();
    embed_gemm<<<dim3(128, 64), 256>>>(x, embW, W_ih, b_ih, b_hh);
    lstm_persistent<<<128, 256, SMEM_BYTES>>>(W_hh);
    out_proj<<<2048, 256>>>(lengths, linW, linb, out);
}

// round 5
// speedup vs baseline: 1.0023x; 1.0023x over previous
#include <cuda_runtime.h>
#include <cstdint>

#define B_   128
#define S_   128
#define I_   300
#define H_   1024
#define G4_  4096
#define CC_  2

#define WSTRIDE 1040            // words per W smem row (1024 + 16 pad; 1040 % 32 == 16)
#define ASTRIDE 80              // words per A-stage smem row (64 + 16 pad; 80 % 32 == 16)
#define SMEM_WORDS (32 * WSTRIDE + 2 * 128 * ASTRIDE)
#define SMEM_BYTES (SMEM_WORDS * 4)   // 215040

// ---------------- static scratch ----------------
__device__ float d_G[(size_t)S_ * B_ * G4_];        // [s][b][4096] input-path preacts (+biases)
__device__ float d_hs[(size_t)(S_ + 1) * B_ * H_];  // h per step, k-interleaved layout; slot 0 = 0
__device__ int   d_ctr;                             // grid barrier counter

// ---------------- helpers ----------------
__device__ __forceinline__ uint32_t f2tf(float x) {
    uint32_t u;
    asm("cvt.rna.tf32.f32 %0, %1;" : "=r"(u) : "f"(x));
    return u;
}

__device__ __forceinline__ void mma_tf32(float c[4], const uint32_t a[4], const uint32_t b[2]) {
    asm volatile(
        "mma.sync.aligned.m16n8k8.row.col.f32.tf32.tf32.f32 "
        "{%0,%1,%2,%3}, {%4,%5,%6,%7}, {%8,%9}, {%0,%1,%2,%3};\n"
        : "+f"(c[0]), "+f"(c[1]), "+f"(c[2]), "+f"(c[3])
        : "r"(a[0]), "r"(a[1]), "r"(a[2]), "r"(a[3]),
          "r"(b[0]), "r"(b[1]));
}

__device__ __forceinline__ float sigf(float x) { return 1.0f / (1.0f + __expf(-x)); }
// safe tanh: no inf/inf NaN at either extreme
__device__ __forceinline__ float tanhf_(float x) { return 2.0f / (1.0f + __expf(-2.0f * x)) - 1.0f; }

// swap bit pairs [1:0] <-> [3:2] within each 16-word block (involution)
__host__ __device__ __forceinline__ int perm16(int k) {
    return (k & ~15) | ((k & 3) << 2) | ((k >> 2) & 3);
}
// smem bank swizzle: word index within row -> physical word (xor by multiples of 4)
__device__ __forceinline__ int swz(int w, int row) {
    return w ^ ((row & 7) << 2) ^ (((w >> 5) & 1) << 2);
}

__device__ __forceinline__ void bar_arrive() {
    asm volatile("red.release.gpu.global.add.s32 [%0], 1;" :: "l"(&d_ctr) : "memory");
}
__device__ __forceinline__ int bar_poll() {
    int v;
    asm volatile("ld.acquire.gpu.global.b32 %0, [%1];" : "=r"(v) : "l"(&d_ctr) : "memory");
    return v;
}

// ---------------- init ----------------
__global__ void init_state() {
    int idx = blockIdx.x * 256 + threadIdx.x;
    if (idx < B_ * H_) d_hs[idx] = 0.0f;     // slot 0 = h0 = 0
    if (idx == 0) d_ctr = 0;
}

// ---------------- input-path GEMM (unchanged from passing R2 kernel) ----------------
__global__ __launch_bounds__(256) void embed_gemm(
    const int* __restrict__ x, const float* __restrict__ embW,
    const float* __restrict__ W_ih, const float* __restrict__ b_ih,
    const float* __restrict__ b_hh)
{
    __shared__ uint32_t As[128][20];
    __shared__ uint32_t Bs[64][20];
    __shared__ int toks[128];

    const int tid = threadIdx.x;
    const int s   = blockIdx.x;
    const int n0  = blockIdx.y * 64;

    if (tid < 128) toks[tid] = x[tid * S_ + s];

    const int w  = tid >> 5, lane = tid & 31;
    const int wm = w >> 1,   wn   = w & 1;
    const int gr = lane >> 2, gc  = lane & 3;
    const int mw = wm * 32,  nw   = wn * 32;

    const int arow = tid >> 1, akb = (tid & 1) * 8;
    const int brow = tid >> 2, bkb = (tid & 3) * 4;

    float acc[2][4][4];
#pragma unroll
    for (int mi = 0; mi < 2; mi++)
#pragma unroll
        for (int ni = 0; ni < 4; ni++)
#pragma unroll
            for (int q = 0; q < 4; q++) acc[mi][ni][q] = 0.0f;

    __syncthreads();

    for (int kt = 0; kt < 19; kt++) {
        const int k0 = kt * 16;
        {
            const float* er = embW + (size_t)toks[arow] * I_;
#pragma unroll
            for (int kk = 0; kk < 8; kk++) {
                int k = k0 + akb + kk;
                As[arow][akb + kk] = f2tf((k < I_) ? er[k] : 0.0f);
            }
        }
        {
            const float* wr = W_ih + (size_t)(n0 + brow) * I_;
#pragma unroll
            for (int kk = 0; kk < 4; kk++) {
                int k = k0 + bkb + kk;
                Bs[brow][bkb + kk] = f2tf((k < I_) ? wr[k] : 0.0f);
            }
        }
        __syncthreads();

#pragma unroll
        for (int ks = 0; ks < 2; ks++) {
            uint32_t a[2][4], b[4][2];
#pragma unroll
            for (int mi = 0; mi < 2; mi++) {
                a[mi][0] = As[mw + mi * 16 + gr][ks * 8 + gc];
                a[mi][1] = As[mw + mi * 16 + 8 + gr][ks * 8 + gc];
                a[mi][2] = As[mw + mi * 16 + gr][ks * 8 + 4 + gc];
                a[mi][3] = As[mw + mi * 16 + 8 + gr][ks * 8 + 4 + gc];
            }
#pragma unroll
            for (int ni = 0; ni < 4; ni++) {
                b[ni][0] = Bs[nw + ni * 8 + gr][ks * 8 + gc];
                b[ni][1] = Bs[nw + ni * 8 + gr][ks * 8 + 4 + gc];
            }
#pragma unroll
            for (int mi = 0; mi < 2; mi++)
#pragma unroll
                for (int ni = 0; ni < 4; ni++)
                    mma_tf32(acc[mi][ni], a[mi], b[ni]);
        }
        __syncthreads();
    }

#pragma unroll
    for (int mi = 0; mi < 2; mi++) {
        const int m0 = mw + mi * 16 + gr;
#pragma unroll
        for (int ni = 0; ni < 4; ni++) {
            const int n = n0 + nw + ni * 8 + gc * 2;
            const float bias0 = b_ih[n] + b_hh[n];
            const float bias1 = b_ih[n + 1] + b_hh[n + 1];
            size_t base0 = ((size_t)s * B_ + m0) * G4_ + n;
            size_t base1 = ((size_t)s * B_ + m0 + 8) * G4_ + n;
            d_G[base0]     = acc[mi][ni][0] + bias0;
            d_G[base0 + 1] = acc[mi][ni][1] + bias1;
            d_G[base1]     = acc[mi][ni][2] + bias0;
            d_G[base1 + 1] = acc[mi][ni][3] + bias1;
        }
    }
}

// ---------------- persistent recurrence: 128 CTAs, all 128 steps ----------------
extern __shared__ float smem_dyn[];

__device__ __forceinline__ void stage_chunk(float* As_buf, const float* hslot,
                                            int chunk, int srow, int shalf)
{
    const float* src = hslot + (size_t)srow * H_ + chunk * 64 + shalf * 32;
    float* dst = As_buf + srow * ASTRIDE;
#pragma unroll
    for (int q = 0; q < 8; q++) {
        float4 v = *reinterpret_cast<const float4*>(src + q * 4);
        int wloc = shalf * 32 + q * 4;
        *reinterpret_cast<float4*>(dst + swz(wloc, srow)) = v;
    }
}

__global__ void __launch_bounds__(256, 1) lstm_persistent(const float* __restrict__ W_hh)
{
    float* Ws = smem_dyn;                   // [32][WSTRIDE] tf32 bits
    float* Ast = smem_dyn + 32 * WSTRIDE;   // [2][128][ASTRIDE]

    const int tid = threadIdx.x;
    const int bid = blockIdx.x;
    const int c0  = bid * 8;

    const int w  = tid >> 5, lane = tid & 31;
    const int gr = lane >> 2, gc = lane & 3;
    const int mw = (w >> 1) * 32;           // 4 m-warps
    const int nw = (w & 1) * 16;            // 2 n-warps

    const int srow = tid >> 1, shalf = tid & 1;

    // ---- preload W slice: smem row p <-> global gate row (gate,jloc) ----
    for (int i = tid; i < 32 * H_; i += 256) {
        int p = i >> 10, k = i & 1023;
        int gate = ((p >> 3) & 1) * 2 + (p & 1);
        int jloc = ((p >> 4) & 1) * 4 + ((p >> 1) & 3);
        float v = W_hh[(size_t)(gate * H_ + c0 + jloc) * H_ + k];
        int wp = perm16(k);
        Ws[p * WSTRIDE + swz(wp, p)] = __uint_as_float(f2tf(v));
    }
    __syncthreads();

    const int jloc_t = (w & 1) * 4 + gc;       // this thread's hidden column (local)
    const int jglob  = c0 + jloc_t;
    const int pglob  = perm16(jglob);          // storage position in interleaved h

    float cReg[4] = {0.0f, 0.0f, 0.0f, 0.0f};

    for (int t = 0; t < S_; t++) {
        const float* hslot = d_hs + (size_t)t * (B_ * H_);

        // stage chunk 0
        stage_chunk(Ast, hslot, 0, srow, shalf);

        // prefetch this thread's 16 G values (in flight during the k-loop)
        float gv[2][2][4];
        {
            const float* Gt = d_G + (size_t)t * B_ * G4_;
#pragma unroll
            for (int mi = 0; mi < 2; mi++)
#pragma unroll
                for (int rs = 0; rs < 2; rs++) {
                    int r = mw + mi * 16 + gr + rs * 8;
                    const float* Gr = Gt + (size_t)r * G4_ + jglob;
#pragma unroll
                    for (int g = 0; g < 4; g++) gv[mi][rs][g] = Gr[g * H_];
                }
        }

        float acc[2][2][4];
#pragma unroll
        for (int mi = 0; mi < 2; mi++)
#pragma unroll
            for (int ni = 0; ni < 2; ni++)
#pragma unroll
                for (int q = 0; q < 4; q++) acc[mi][ni][q] = 0.0f;

        __syncthreads();

        for (int c = 0; c < 16; c++) {
            if (c < 15)
                stage_chunk(Ast + ((c + 1) & 1) * (128 * ASTRIDE), hslot, c + 1, srow, shalf);

            const float* Ab = Ast + (c & 1) * (128 * ASTRIDE);
#pragma unroll
            for (int gl = 0; gl < 4; gl++) {
                const int wbase = gl * 16 + gc * 4;
                uint4 av[2][2], bv[2];
#pragma unroll
                for (int mi = 0; mi < 2; mi++) {
                    const int R0 = mw + mi * 16 + gr;
                    av[mi][0] = *reinterpret_cast<const uint4*>(Ab + R0 * ASTRIDE + swz(wbase, R0));
                    av[mi][1] = *reinterpret_cast<const uint4*>(Ab + (R0 + 8) * ASTRIDE + swz(wbase, R0 + 8));
                }
                const int wfull = (c * 4 + gl) * 16 + gc * 4;
#pragma unroll
                for (int ni = 0; ni < 2; ni++) {
                    const int nb = nw + ni * 8 + gr;
                    bv[ni] = *reinterpret_cast<const uint4*>(Ws + nb * WSTRIDE + swz(wfull, nb));
                }
                // k-chunk 0: words .x (k=gc), .y (k=4+gc)
                {
                    uint32_t b0[2] = {bv[0].x, bv[0].y};
                    uint32_t b1[2] = {bv[1].x, bv[1].y};
#pragma unroll
                    for (int mi = 0; mi < 2; mi++) {
                        uint32_t a[4] = {av[mi][0].x, av[mi][1].x, av[mi][0].y, av[mi][1].y};
                        mma_tf32(acc[mi][0], a, b0);
                        mma_tf32(acc[mi][1], a, b1);
                    }
                }
                // k-chunk 1: words .z (k=8+gc), .w (k=12+gc)
                {
                    uint32_t b0[2] = {bv[0].z, bv[0].w};
                    uint32_t b1[2] = {bv[1].z, bv[1].w};
#pragma unroll
                    for (int mi = 0; mi < 2; mi++) {
                        uint32_t a[4] = {av[mi][0].z, av[mi][1].z, av[mi][0].w, av[mi][1].w};
                        mma_tf32(acc[mi][0], a, b0);
                        mma_tf32(acc[mi][1], a, b1);
                    }
                }
            }
            __syncthreads();
        }

        // ---- epilogue: add G, LSTM cell (c in regs), write h ----
        float* hout = d_hs + (size_t)(t + 1) * (B_ * H_);
#pragma unroll
        for (int mi = 0; mi < 2; mi++)
#pragma unroll
            for (int rs = 0; rs < 2; rs++) {
                const int r = mw + mi * 16 + gr + rs * 8;
                const float ig = acc[mi][0][rs * 2]     + gv[mi][rs][0];
                const float fg = acc[mi][0][rs * 2 + 1] + gv[mi][rs][1];
                const float gg = acc[mi][1][rs * 2]     + gv[mi][rs][2];
                const float og = acc[mi][1][rs * 2 + 1] + gv[mi][rs][3];
                const int ci = mi * 2 + rs;
                const float cn = sigf(fg) * cReg[ci] + sigf(ig) * tanhf_(gg);
                cReg[ci] = cn;
                const float h = sigf(og) * tanhf_(cn);
                hout[(size_t)r * H_ + pglob] = __uint_as_float(f2tf(h));
            }

        // ---- grid barrier ----
        __syncthreads();
        if (tid == 0) {
            bar_arrive();
            const int tgt = 128 * (t + 1);
            while (bar_poll() < tgt) { __nanosleep(40); }
        }
        __syncthreads();
    }
}

// ---------------- output projection + length mask ----------------
__global__ __launch_bounds__(256) void out_proj(
    const int* __restrict__ lengths, const float* __restrict__ linW,
    const float* __restrict__ linb, float* __restrict__ out)
{
    const int gw   = (blockIdx.x * 256 + threadIdx.x) >> 5;
    const int lane = threadIdx.x & 31;
    const int b = gw >> 7;
    const int s = gw & 127;

    const float* __restrict__ h = d_hs + ((size_t)(s + 1) * B_ + b) * H_;
    float s0 = 0.0f, s1 = 0.0f;
#pragma unroll 8
    for (int p = lane; p < H_; p += 32) {
        const int k = perm16(p);              // stored position p holds hidden index perm16(p)
        const float hv = h[p];
        s0 += hv * linW[k];
        s1 += hv * linW[H_ + k];
    }
#pragma unroll
    for (int o = 16; o > 0; o >>= 1) {
        s0 += __shfl_xor_sync(0xFFFFFFFFu, s0, o);
        s1 += __shfl_xor_sync(0xFFFFFFFFu, s1, o);
    }
    if (lane == 0) {
        float* orow = out + ((size_t)b * S_ + s) * CC_;
        if (s < lengths[b]) {
            orow[0] = s0 + linb[0];
            orow[1] = s1 + linb[1];
        } else {
            orow[0] = 1.0f;
            orow[1] = 0.0f;
        }
    }
}

// ---------------- launch ----------------
extern "C" void kernel_launch(void* const* d_in, const int* in_sizes, int n_in,
                              void* d_out, int out_size) {
    const int*   x       = (const int*)d_in[0];
    const int*   lengths = (const int*)d_in[1];
    const float* embW    = (const float*)d_in[2];
    const float* W_ih    = (const float*)d_in[3];
    const float* W_hh    = (const float*)d_in[4];
    const float* b_ih    = (const float*)d_in[5];
    const float* b_hh    = (const float*)d_in[6];
    const float* linW    = (const float*)d_in[7];
    const float* linb    = (const float*)d_in[8];
    float*       out     = (float*)d_out;

    static bool attr_done = false;
    if (!attr_done) {
        cudaFuncSetAttribute(lstm_persistent,
                             cudaFuncAttributeMaxDynamicSharedMemorySize, SMEM_BYTES);
        attr_done = true;
    }

    init_state<<<512, 256>>>();
    embed_gemm<<<dim3(128, 64), 256>>>(x, embW, W_ih, b_ih, b_hh);
    lstm_persistent<<<128, 256, SMEM_BYTES>>>(W_hh);
    out_proj<<<2048, 256>>>(lengths, linW, linb, out);
}

// round 6
// speedup vs baseline: 1.3832x; 1.3800x over previous
#include <cuda_runtime.h>
#include <cstdint>

#define B_   128
#define S_   128
#define I_   300
#define H_   1024
#define G4_  4096
#define CC_  2

#define WSTRIDE 1040
#define ASTRIDE 80
#define SMEM_WORDS (32 * WSTRIDE + 2 * 128 * ASTRIDE)
#define SMEM_BYTES (SMEM_WORDS * 4)

__device__ float d_G[(size_t)S_ * B_ * G4_];
__device__ float d_hs[(size_t)(S_ + 1) * B_ * H_];
__device__ int   d_ctr;

__device__ __forceinline__ uint32_t f2tf(float x) {
    uint32_t u; asm("cvt.rna.tf32.f32 %0, %1;" : "=r"(u) : "f"(x)); return u;
}
__device__ __forceinline__ uint32_t smem_u32(const void* p) {
    uint32_t a;
    asm("{ .reg .u64 t; cvta.to.shared.u64 t, %1; cvt.u32.u64 %0, t; }" : "=r"(a) : "l"(p));
    return a;
}
__device__ __forceinline__ void mma_tf32(float c[4], const uint32_t a[4], const uint32_t b[2]) {
    asm volatile(
        "mma.sync.aligned.m16n8k8.row.col.f32.tf32.tf32.f32 "
        "{%0,%1,%2,%3}, {%4,%5,%6,%7}, {%8,%9}, {%0,%1,%2,%3};\n"
        : "+f"(c[0]), "+f"(c[1]), "+f"(c[2]), "+f"(c[3])
        : "r"(a[0]), "r"(a[1]), "r"(a[2]), "r"(a[3]), "r"(b[0]), "r"(b[1]));
}
__device__ __forceinline__ float sigf(float x)   { return 1.0f / (1.0f + __expf(-x)); }
__device__ __forceinline__ float tanhf_(float x) { return 2.0f / (1.0f + __expf(-2.0f * x)) - 1.0f; }
__host__ __device__ __forceinline__ int perm16(int k) {
    return (k & ~15) | ((k & 3) << 2) | ((k >> 2) & 3);
}
__device__ __forceinline__ int swz(int w, int row) {
    return w ^ ((row & 7) << 2) ^ (((w >> 5) & 1) << 2);
}
__device__ __forceinline__ void bar_arrive() {
    asm volatile("red.release.gpu.global.add.s32 [%0], 1;" :: "l"(&d_ctr) : "memory");
}
__device__ __forceinline__ int bar_poll() {
    int v;
    asm volatile("ld.acquire.gpu.global.b32 %0, [%1];" : "=r"(v) : "l"(&d_ctr) : "memory");
    return v;
}

__global__ void init_state() {
    int idx = blockIdx.x * 256 + threadIdx.x;
    if (idx < B_ * H_) d_hs[idx] = 0.0f;
    if (idx == 0) d_ctr = 0;
}

// ---------------- input-path GEMM (unchanged, known-good) ----------------
__global__ __launch_bounds__(256) void embed_gemm(
    const int* __restrict__ x, const float* __restrict__ embW,
    const float* __restrict__ W_ih, const float* __restrict__ b_ih,
    const float* __restrict__ b_hh)
{
    __shared__ uint32_t As[128][20];
    __shared__ uint32_t Bs[64][20];
    __shared__ int toks[128];

    const int tid = threadIdx.x;
    const int s   = blockIdx.x;
    const int n0  = blockIdx.y * 64;

    if (tid < 128) toks[tid] = x[tid * S_ + s];

    const int w  = tid >> 5, lane = tid & 31;
    const int wm = w >> 1,   wn   = w & 1;
    const int gr = lane >> 2, gc  = lane & 3;
    const int mw = wm * 32,  nw   = wn * 32;

    const int arow = tid >> 1, akb = (tid & 1) * 8;
    const int brow = tid >> 2, bkb = (tid & 3) * 4;

    float acc[2][4][4];
#pragma unroll
    for (int mi = 0; mi < 2; mi++)
#pragma unroll
        for (int ni = 0; ni < 4; ni++)
#pragma unroll
            for (int q = 0; q < 4; q++) acc[mi][ni][q] = 0.0f;

    __syncthreads();

    for (int kt = 0; kt < 19; kt++) {
        const int k0 = kt * 16;
        {
            const float* er = embW + (size_t)toks[arow] * I_;
#pragma unroll
            for (int kk = 0; kk < 8; kk++) {
                int k = k0 + akb + kk;
                As[arow][akb + kk] = f2tf((k < I_) ? er[k] : 0.0f);
            }
        }
        {
            const float* wr = W_ih + (size_t)(n0 + brow) * I_;
#pragma unroll
            for (int kk = 0; kk < 4; kk++) {
                int k = k0 + bkb + kk;
                Bs[brow][bkb + kk] = f2tf((k < I_) ? wr[k] : 0.0f);
            }
        }
        __syncthreads();

#pragma unroll
        for (int ks = 0; ks < 2; ks++) {
            uint32_t a[2][4], b[4][2];
#pragma unroll
            for (int mi = 0; mi < 2; mi++) {
                a[mi][0] = As[mw + mi * 16 + gr][ks * 8 + gc];
                a[mi][1] = As[mw + mi * 16 + 8 + gr][ks * 8 + gc];
                a[mi][2] = As[mw + mi * 16 + gr][ks * 8 + 4 + gc];
                a[mi][3] = As[mw + mi * 16 + 8 + gr][ks * 8 + 4 + gc];
            }
#pragma unroll
            for (int ni = 0; ni < 4; ni++) {
                b[ni][0] = Bs[nw + ni * 8 + gr][ks * 8 + gc];
                b[ni][1] = Bs[nw + ni * 8 + gr][ks * 8 + 4 + gc];
            }
#pragma unroll
            for (int mi = 0; mi < 2; mi++)
#pragma unroll
                for (int ni = 0; ni < 4; ni++)
                    mma_tf32(acc[mi][ni], a[mi], b[ni]);
        }
        __syncthreads();
    }

#pragma unroll
    for (int mi = 0; mi < 2; mi++) {
        const int m0 = mw + mi * 16 + gr;
#pragma unroll
        for (int ni = 0; ni < 4; ni++) {
            const int n = n0 + nw + ni * 8 + gc * 2;
            const float bias0 = b_ih[n] + b_hh[n];
            const float bias1 = b_ih[n + 1] + b_hh[n + 1];
            size_t base0 = ((size_t)s * B_ + m0) * G4_ + n;
            size_t base1 = ((size_t)s * B_ + m0 + 8) * G4_ + n;
            d_G[base0]     = acc[mi][ni][0] + bias0;
            d_G[base0 + 1] = acc[mi][ni][1] + bias1;
            d_G[base1]     = acc[mi][ni][2] + bias0;
            d_G[base1 + 1] = acc[mi][ni][3] + bias1;
        }
    }
}

// ---------------- persistent recurrence (cp.async staging) ----------------
extern __shared__ float smem_dyn[];

__device__ __forceinline__ void stage_async(float* As_buf, const float* hslot,
                                            int chunk, int srow, int shalf)
{
    const float* src = hslot + (size_t)srow * H_ + chunk * 64 + shalf * 32;
    float* dst = As_buf + srow * ASTRIDE;
#pragma unroll
    for (int q = 0; q < 8; q++) {
        int wloc = shalf * 32 + q * 4;
        uint32_t da = smem_u32(dst + swz(wloc, srow));
        asm volatile("cp.async.cg.shared.global [%0], [%1], 16;"
                     :: "r"(da), "l"(src + q * 4) : "memory");
    }
}

__global__ void __launch_bounds__(256, 1) lstm_persistent(const float* __restrict__ W_hh)
{
    float* Ws  = smem_dyn;
    float* Ast = smem_dyn + 32 * WSTRIDE;

    const int tid = threadIdx.x;
    const int bid = blockIdx.x;
    const int c0  = bid * 8;

    const int w  = tid >> 5, lane = tid & 31;
    const int gr = lane >> 2, gc = lane & 3;
    const int mw = (w >> 1) * 32;
    const int nw = (w & 1) * 16;

    const int srow = tid >> 1, shalf = tid & 1;

    for (int i = tid; i < 32 * H_; i += 256) {
        int p = i >> 10, k = i & 1023;
        int gate = ((p >> 3) & 1) * 2 + (p & 1);
        int jloc = ((p >> 4) & 1) * 4 + ((p >> 1) & 3);
        float v = W_hh[(size_t)(gate * H_ + c0 + jloc) * H_ + k];
        int wp = perm16(k);
        Ws[p * WSTRIDE + swz(wp, p)] = __uint_as_float(f2tf(v));
    }
    __syncthreads();

    const int jloc_t = (w & 1) * 4 + gc;
    const int jglob  = c0 + jloc_t;
    const int pglob  = perm16(jglob);

    float cReg[4] = {0.0f, 0.0f, 0.0f, 0.0f};

    for (int t = 0; t < S_; t++) {
        const float* hslot = d_hs + (size_t)t * (B_ * H_);

        // prologue: async-stage chunk 0
        stage_async(Ast, hslot, 0, srow, shalf);
        asm volatile("cp.async.commit_group;" ::: "memory");

        // G prefetch (in flight under the k-loop)
        float gv[2][2][4];
        {
            const float* Gt = d_G + (size_t)t * B_ * G4_;
#pragma unroll
            for (int mi = 0; mi < 2; mi++)
#pragma unroll
                for (int rs = 0; rs < 2; rs++) {
                    int r = mw + mi * 16 + gr + rs * 8;
                    const float* Gr = Gt + (size_t)r * G4_ + jglob;
#pragma unroll
                    for (int g = 0; g < 4; g++) gv[mi][rs][g] = Gr[g * H_];
                }
        }

        float acc[2][2][4];
#pragma unroll
        for (int mi = 0; mi < 2; mi++)
#pragma unroll
            for (int ni = 0; ni < 2; ni++)
#pragma unroll
                for (int q = 0; q < 4; q++) acc[mi][ni][q] = 0.0f;

        for (int c = 0; c < 16; c++) {
            if (c < 15) {
                stage_async(Ast + ((c + 1) & 1) * (128 * ASTRIDE), hslot, c + 1, srow, shalf);
                asm volatile("cp.async.commit_group;" ::: "memory");
                asm volatile("cp.async.wait_group 1;" ::: "memory");
            } else {
                asm volatile("cp.async.wait_group 0;" ::: "memory");
            }
            __syncthreads();   // chunk c visible to all warps

            const float* Ab = Ast + (c & 1) * (128 * ASTRIDE);
#pragma unroll
            for (int gl = 0; gl < 4; gl++) {
                const int wbase = gl * 16 + gc * 4;
                uint4 av[2][2], bv[2];
#pragma unroll
                for (int mi = 0; mi < 2; mi++) {
                    const int R0 = mw + mi * 16 + gr;
                    av[mi][0] = *reinterpret_cast<const uint4*>(Ab + R0 * ASTRIDE + swz(wbase, R0));
                    av[mi][1] = *reinterpret_cast<const uint4*>(Ab + (R0 + 8) * ASTRIDE + swz(wbase, R0 + 8));
                }
                const int wfull = (c * 4 + gl) * 16 + gc * 4;
#pragma unroll
                for (int ni = 0; ni < 2; ni++) {
                    const int nb = nw + ni * 8 + gr;
                    bv[ni] = *reinterpret_cast<const uint4*>(Ws + nb * WSTRIDE + swz(wfull, nb));
                }
                {
                    uint32_t b0[2] = {bv[0].x, bv[0].y};
                    uint32_t b1[2] = {bv[1].x, bv[1].y};
#pragma unroll
                    for (int mi = 0; mi < 2; mi++) {
                        uint32_t a[4] = {av[mi][0].x, av[mi][1].x, av[mi][0].y, av[mi][1].y};
                        mma_tf32(acc[mi][0], a, b0);
                        mma_tf32(acc[mi][1], a, b1);
                    }
                }
                {
                    uint32_t b0[2] = {bv[0].z, bv[0].w};
                    uint32_t b1[2] = {bv[1].z, bv[1].w};
#pragma unroll
                    for (int mi = 0; mi < 2; mi++) {
                        uint32_t a[4] = {av[mi][0].z, av[mi][1].z, av[mi][0].w, av[mi][1].w};
                        mma_tf32(acc[mi][0], a, b0);
                        mma_tf32(acc[mi][1], a, b1);
                    }
                }
            }
            __syncthreads();   // all reads of buffer (c&1) done before overwrite
        }

        float* hout = d_hs + (size_t)(t + 1) * (B_ * H_);
#pragma unroll
        for (int mi = 0; mi < 2; mi++)
#pragma unroll
            for (int rs = 0; rs < 2; rs++) {
                const int r = mw + mi * 16 + gr + rs * 8;
                const float ig = acc[mi][0][rs * 2]     + gv[mi][rs][0];
                const float fg = acc[mi][0][rs * 2 + 1] + gv[mi][rs][1];
                const float gg = acc[mi][1][rs * 2]     + gv[mi][rs][2];
                const float og = acc[mi][1][rs * 2 + 1] + gv[mi][rs][3];
                const int ci = mi * 2 + rs;
                const float cn = sigf(fg) * cReg[ci] + sigf(ig) * tanhf_(gg);
                cReg[ci] = cn;
                const float h = sigf(og) * tanhf_(cn);
                hout[(size_t)r * H_ + pglob] = __uint_as_float(f2tf(h));
            }

        __syncthreads();
        if (tid == 0) {
            bar_arrive();
            const int tgt = 128 * (t + 1);
            while (bar_poll() < tgt) { __nanosleep(40); }
        }
        __syncthreads();
    }
}

// ---------------- output projection + mask ----------------
__global__ __launch_bounds__(256) void out_proj(
    const int* __restrict__ lengths, const float* __restrict__ linW,
    const float* __restrict__ linb, float* __restrict__ out)
{
    const int gw   = (blockIdx.x * 256 + threadIdx.x) >> 5;
    const int lane = threadIdx.x & 31;
    const int b = gw >> 7;
    const int s = gw & 127;

    const float* __restrict__ h = d_hs + ((size_t)(s + 1) * B_ + b) * H_;
    float s0 = 0.0f, s1 = 0.0f;
#pragma unroll 8
    for (int p = lane; p < H_; p += 32) {
        const int k = perm16(p);
        const float hv = h[p];
        s0 += hv * linW[k];
        s1 += hv * linW[H_ + k];
    }
#pragma unroll
    for (int o = 16; o > 0; o >>= 1) {
        s0 += __shfl_xor_sync(0xFFFFFFFFu, s0, o);
        s1 += __shfl_xor_sync(0xFFFFFFFFu, s1, o);
    }
    if (lane == 0) {
        float* orow = out + ((size_t)b * S_ + s) * CC_;
        if (s < lengths[b]) {
            orow[0] = s0 + linb[0];
            orow[1] = s1 + linb[1];
        } else {
            orow[0] = 1.0f;
            orow[1] = 0.0f;
        }
    }
}

extern "C" void kernel_launch(void* const* d_in, const int* in_sizes, int n_in,
                              void* d_out, int out_size) {
    const int*   x       = (const int*)d_in[0];
    const int*   lengths = (const int*)d_in[1];
    const float* embW    = (const float*)d_in[2];
    const float* W_ih    = (const float*)d_in[3];
    const float* W_hh    = (const float*)d_in[4];
    const float* b_ih    = (const float*)d_in[5];
    const float* b_hh    = (const float*)d_in[6];
    const float* linW    = (const float*)d_in[7];
    const float* linb    = (const float*)d_in[8];
    float*       out     = (float*)d_out;

    static bool attr_done = false;
    if (!attr_done) {
        cudaFuncSetAttribute(lstm_persistent,
                             cudaFuncAttributeMaxDynamicSharedMemorySize, SMEM_BYTES);
        attr_done = true;
    }

    init_state<<<512, 256>>>();
    embed_gemm<<<dim3(128, 64), 256>>>(x, embW, W_ih, b_ih, b_hh);
    lstm_persistent<<<128, 256, SMEM_BYTES>>>(W_hh);
    out_proj<<<2048, 256>>>(lengths, linW, linb, out);
}

// round 7
// speedup vs baseline: 1.5232x; 1.1012x over previous
#include <cuda_runtime.h>
#include <cstdint>

#define B_   128
#define S_   128
#define I_   300
#define H_   1024
#define G4_  4096
#define CC_  2

#define WSTRIDE 1040
#define ASTRIDE 80
#define SMEM_WORDS (32 * WSTRIDE + 2 * 128 * ASTRIDE)
#define SMEM_BYTES (SMEM_WORDS * 4)

__device__ float d_G[(size_t)S_ * B_ * G4_];
__device__ float d_hs[(size_t)(S_ + 1) * B_ * H_];
__device__ int   d_ctr;

__device__ __forceinline__ uint32_t f2tf(float x) {
    uint32_t u; asm("cvt.rna.tf32.f32 %0, %1;" : "=r"(u) : "f"(x)); return u;
}
__device__ __forceinline__ uint32_t f2tf_u(uint32_t raw) {
    return f2tf(__uint_as_float(raw));
}
__device__ __forceinline__ uint32_t smem_u32(const void* p) {
    uint32_t a;
    asm("{ .reg .u64 t; cvta.to.shared.u64 t, %1; cvt.u32.u64 %0, t; }" : "=r"(a) : "l"(p));
    return a;
}
__device__ __forceinline__ void mma_tf32(float c[4], const uint32_t a[4], const uint32_t b[2]) {
    asm volatile(
        "mma.sync.aligned.m16n8k8.row.col.f32.tf32.tf32.f32 "
        "{%0,%1,%2,%3}, {%4,%5,%6,%7}, {%8,%9}, {%0,%1,%2,%3};\n"
        : "+f"(c[0]), "+f"(c[1]), "+f"(c[2]), "+f"(c[3])
        : "r"(a[0]), "r"(a[1]), "r"(a[2]), "r"(a[3]), "r"(b[0]), "r"(b[1]));
}
__device__ __forceinline__ float sigf(float x)   { return 1.0f / (1.0f + __expf(-x)); }
__device__ __forceinline__ float tanhf_(float x) { return 2.0f / (1.0f + __expf(-2.0f * x)) - 1.0f; }
__host__ __device__ __forceinline__ int perm16(int k) {
    return (k & ~15) | ((k & 3) << 2) | ((k >> 2) & 3);
}
__device__ __forceinline__ int swz(int w, int row) {
    return w ^ ((row & 7) << 2) ^ (((w >> 5) & 1) << 2);
}
__device__ __forceinline__ void bar_arrive() {
    asm volatile("red.release.gpu.global.add.s32 [%0], 1;" :: "l"(&d_ctr) : "memory");
}
__device__ __forceinline__ int bar_poll() {
    int v;
    asm volatile("ld.acquire.gpu.global.b32 %0, [%1];" : "=r"(v) : "l"(&d_ctr) : "memory");
    return v;
}
__device__ __forceinline__ void cpa16(uint32_t dst, const void* src, int src_bytes) {
    asm volatile("cp.async.cg.shared.global [%0], [%1], 16, %2;"
                 :: "r"(dst), "l"(src), "r"(src_bytes) : "memory");
}

__global__ void init_state() {
    int idx = blockIdx.x * 256 + threadIdx.x;
    if (idx < B_ * H_) d_hs[idx] = 0.0f;
    if (idx == 0) d_ctr = 0;
}

// ---------------- input-path GEMM (cp.async pipelined) ----------------
__global__ __launch_bounds__(256) void embed_gemm(
    const int* __restrict__ x, const float* __restrict__ embW,
    const float* __restrict__ W_ih, const float* __restrict__ b_ih,
    const float* __restrict__ b_hh)
{
    __shared__ uint32_t As[2][128][20];
    __shared__ uint32_t Bs[2][64][20];
    __shared__ int toks[128];

    const int tid = threadIdx.x;
    const int s   = blockIdx.x;
    const int n0  = blockIdx.y * 64;

    if (tid < 128) toks[tid] = x[tid * S_ + s];

    const int w  = tid >> 5, lane = tid & 31;
    const int wm = w >> 1,   wn   = w & 1;
    const int gr = lane >> 2, gc  = lane & 3;
    const int mw = wm * 32,  nw   = wn * 32;

    const int arow = tid >> 1, akb = (tid & 1) * 8;
    const int brow = tid >> 2, bkb = (tid & 3) * 4;

    __syncthreads();   // toks ready (staging reads them)

    const float* aptr = embW + (size_t)toks[arow] * I_;
    const float* bptr = W_ih + (size_t)(n0 + brow) * I_;

    // stage k-tile kt into buffer bi (raw fp32 bits; zero-fill past I_)
    auto stage = [&](int kt, int bi) {
        const int k0 = kt * 16;
#pragma unroll
        for (int q = 0; q < 2; q++) {
            int kq = k0 + akb + q * 4;
            int sz = (I_ - kq) * 4; sz = sz < 0 ? 0 : (sz > 16 ? 16 : sz);
            cpa16(smem_u32(&As[bi][arow][akb + q * 4]), aptr + (sz ? kq : 0), sz);
        }
        {
            int kq = k0 + bkb;
            int sz = (I_ - kq) * 4; sz = sz < 0 ? 0 : (sz > 16 ? 16 : sz);
            cpa16(smem_u32(&Bs[bi][brow][bkb]), bptr + (sz ? kq : 0), sz);
        }
        asm volatile("cp.async.commit_group;" ::: "memory");
    };

    float acc[2][4][4];
#pragma unroll
    for (int mi = 0; mi < 2; mi++)
#pragma unroll
        for (int ni = 0; ni < 4; ni++)
#pragma unroll
            for (int q = 0; q < 4; q++) acc[mi][ni][q] = 0.0f;

    stage(0, 0);

    for (int kt = 0; kt < 19; kt++) {
        const int bi = kt & 1;
        if (kt < 18) {
            stage(kt + 1, bi ^ 1);
            asm volatile("cp.async.wait_group 1;" ::: "memory");
        } else {
            asm volatile("cp.async.wait_group 0;" ::: "memory");
        }
        __syncthreads();

#pragma unroll
        for (int ks = 0; ks < 2; ks++) {
            uint32_t a[2][4], b[4][2];
#pragma unroll
            for (int mi = 0; mi < 2; mi++) {
                a[mi][0] = f2tf_u(As[bi][mw + mi * 16 + gr][ks * 8 + gc]);
                a[mi][1] = f2tf_u(As[bi][mw + mi * 16 + 8 + gr][ks * 8 + gc]);
                a[mi][2] = f2tf_u(As[bi][mw + mi * 16 + gr][ks * 8 + 4 + gc]);
                a[mi][3] = f2tf_u(As[bi][mw + mi * 16 + 8 + gr][ks * 8 + 4 + gc]);
            }
#pragma unroll
            for (int ni = 0; ni < 4; ni++) {
                b[ni][0] = f2tf_u(Bs[bi][nw + ni * 8 + gr][ks * 8 + gc]);
                b[ni][1] = f2tf_u(Bs[bi][nw + ni * 8 + gr][ks * 8 + 4 + gc]);
            }
#pragma unroll
            for (int mi = 0; mi < 2; mi++)
#pragma unroll
                for (int ni = 0; ni < 4; ni++)
                    mma_tf32(acc[mi][ni], a[mi], b[ni]);
        }
        __syncthreads();
    }

#pragma unroll
    for (int mi = 0; mi < 2; mi++) {
        const int m0 = mw + mi * 16 + gr;
#pragma unroll
        for (int ni = 0; ni < 4; ni++) {
            const int n = n0 + nw + ni * 8 + gc * 2;
            const float bias0 = b_ih[n] + b_hh[n];
            const float bias1 = b_ih[n + 1] + b_hh[n + 1];
            size_t base0 = ((size_t)s * B_ + m0) * G4_ + n;
            size_t base1 = ((size_t)s * B_ + m0 + 8) * G4_ + n;
            d_G[base0]     = acc[mi][ni][0] + bias0;
            d_G[base0 + 1] = acc[mi][ni][1] + bias1;
            d_G[base1]     = acc[mi][ni][2] + bias0;
            d_G[base1 + 1] = acc[mi][ni][3] + bias1;
        }
    }
}

// ---------------- persistent recurrence (unchanged from R5 win) ----------------
extern __shared__ float smem_dyn[];

__device__ __forceinline__ void stage_async(float* As_buf, const float* hslot,
                                            int chunk, int srow, int shalf)
{
    const float* src = hslot + (size_t)srow * H_ + chunk * 64 + shalf * 32;
    float* dst = As_buf + srow * ASTRIDE;
#pragma unroll
    for (int q = 0; q < 8; q++) {
        int wloc = shalf * 32 + q * 4;
        uint32_t da = smem_u32(dst + swz(wloc, srow));
        asm volatile("cp.async.cg.shared.global [%0], [%1], 16;"
                     :: "r"(da), "l"(src + q * 4) : "memory");
    }
}

__global__ void __launch_bounds__(256, 1) lstm_persistent(const float* __restrict__ W_hh)
{
    float* Ws  = smem_dyn;
    float* Ast = smem_dyn + 32 * WSTRIDE;

    const int tid = threadIdx.x;
    const int bid = blockIdx.x;
    const int c0  = bid * 8;

    const int w  = tid >> 5, lane = tid & 31;
    const int gr = lane >> 2, gc = lane & 3;
    const int mw = (w >> 1) * 32;
    const int nw = (w & 1) * 16;

    const int srow = tid >> 1, shalf = tid & 1;

    for (int i = tid; i < 32 * H_; i += 256) {
        int p = i >> 10, k = i & 1023;
        int gate = ((p >> 3) & 1) * 2 + (p & 1);
        int jloc = ((p >> 4) & 1) * 4 + ((p >> 1) & 3);
        float v = W_hh[(size_t)(gate * H_ + c0 + jloc) * H_ + k];
        int wp = perm16(k);
        Ws[p * WSTRIDE + swz(wp, p)] = __uint_as_float(f2tf(v));
    }
    __syncthreads();

    const int jloc_t = (w & 1) * 4 + gc;
    const int jglob  = c0 + jloc_t;
    const int pglob  = perm16(jglob);

    float cReg[4] = {0.0f, 0.0f, 0.0f, 0.0f};

    for (int t = 0; t < S_; t++) {
        const float* hslot = d_hs + (size_t)t * (B_ * H_);

        stage_async(Ast, hslot, 0, srow, shalf);
        asm volatile("cp.async.commit_group;" ::: "memory");

        float gv[2][2][4];
        {
            const float* Gt = d_G + (size_t)t * B_ * G4_;
#pragma unroll
            for (int mi = 0; mi < 2; mi++)
#pragma unroll
                for (int rs = 0; rs < 2; rs++) {
                    int r = mw + mi * 16 + gr + rs * 8;
                    const float* Gr = Gt + (size_t)r * G4_ + jglob;
#pragma unroll
                    for (int g = 0; g < 4; g++) gv[mi][rs][g] = Gr[g * H_];
                }
        }

        float acc[2][2][4];
#pragma unroll
        for (int mi = 0; mi < 2; mi++)
#pragma unroll
            for (int ni = 0; ni < 2; ni++)
#pragma unroll
                for (int q = 0; q < 4; q++) acc[mi][ni][q] = 0.0f;

        for (int c = 0; c < 16; c++) {
            if (c < 15) {
                stage_async(Ast + ((c + 1) & 1) * (128 * ASTRIDE), hslot, c + 1, srow, shalf);
                asm volatile("cp.async.commit_group;" ::: "memory");
                asm volatile("cp.async.wait_group 1;" ::: "memory");
            } else {
                asm volatile("cp.async.wait_group 0;" ::: "memory");
            }
            __syncthreads();

            const float* Ab = Ast + (c & 1) * (128 * ASTRIDE);
#pragma unroll
            for (int gl = 0; gl < 4; gl++) {
                const int wbase = gl * 16 + gc * 4;
                uint4 av[2][2], bv[2];
#pragma unroll
                for (int mi = 0; mi < 2; mi++) {
                    const int R0 = mw + mi * 16 + gr;
                    av[mi][0] = *reinterpret_cast<const uint4*>(Ab + R0 * ASTRIDE + swz(wbase, R0));
                    av[mi][1] = *reinterpret_cast<const uint4*>(Ab + (R0 + 8) * ASTRIDE + swz(wbase, R0 + 8));
                }
                const int wfull = (c * 4 + gl) * 16 + gc * 4;
#pragma unroll
                for (int ni = 0; ni < 2; ni++) {
                    const int nb = nw + ni * 8 + gr;
                    bv[ni] = *reinterpret_cast<const uint4*>(Ws + nb * WSTRIDE + swz(wfull, nb));
                }
                {
                    uint32_t b0[2] = {bv[0].x, bv[0].y};
                    uint32_t b1[2] = {bv[1].x, bv[1].y};
#pragma unroll
                    for (int mi = 0; mi < 2; mi++) {
                        uint32_t a[4] = {av[mi][0].x, av[mi][1].x, av[mi][0].y, av[mi][1].y};
                        mma_tf32(acc[mi][0], a, b0);
                        mma_tf32(acc[mi][1], a, b1);
                    }
                }
                {
                    uint32_t b0[2] = {bv[0].z, bv[0].w};
                    uint32_t b1[2] = {bv[1].z, bv[1].w};
#pragma unroll
                    for (int mi = 0; mi < 2; mi++) {
                        uint32_t a[4] = {av[mi][0].z, av[mi][1].z, av[mi][0].w, av[mi][1].w};
                        mma_tf32(acc[mi][0], a, b0);
                        mma_tf32(acc[mi][1], a, b1);
                    }
                }
            }
            __syncthreads();
        }

        float* hout = d_hs + (size_t)(t + 1) * (B_ * H_);
#pragma unroll
        for (int mi = 0; mi < 2; mi++)
#pragma unroll
            for (int rs = 0; rs < 2; rs++) {
                const int r = mw + mi * 16 + gr + rs * 8;
                const float ig = acc[mi][0][rs * 2]     + gv[mi][rs][0];
                const float fg = acc[mi][0][rs * 2 + 1] + gv[mi][rs][1];
                const float gg = acc[mi][1][rs * 2]     + gv[mi][rs][2];
                const float og = acc[mi][1][rs * 2 + 1] + gv[mi][rs][3];
                const int ci = mi * 2 + rs;
                const float cn = sigf(fg) * cReg[ci] + sigf(ig) * tanhf_(gg);
                cReg[ci] = cn;
                const float h = sigf(og) * tanhf_(cn);
                hout[(size_t)r * H_ + pglob] = __uint_as_float(f2tf(h));
            }

        __syncthreads();
        if (tid == 0) {
            bar_arrive();
            const int tgt = 128 * (t + 1);
            while (bar_poll() < tgt) { __nanosleep(40); }
        }
        __syncthreads();
    }
}

// ---------------- output projection + mask ----------------
__global__ __launch_bounds__(256) void out_proj(
    const int* __restrict__ lengths, const float* __restrict__ linW,
    const float* __restrict__ linb, float* __restrict__ out)
{
    const int gw   = (blockIdx.x * 256 + threadIdx.x) >> 5;
    const int lane = threadIdx.x & 31;
    const int b = gw >> 7;
    const int s = gw & 127;

    const float* __restrict__ h = d_hs + ((size_t)(s + 1) * B_ + b) * H_;
    float s0 = 0.0f, s1 = 0.0f;
#pragma unroll 8
    for (int p = lane; p < H_; p += 32) {
        const int k = perm16(p);
        const float hv = h[p];
        s0 += hv * linW[k];
        s1 += hv * linW[H_ + k];
    }
#pragma unroll
    for (int o = 16; o > 0; o >>= 1) {
        s0 += __shfl_xor_sync(0xFFFFFFFFu, s0, o);
        s1 += __shfl_xor_sync(0xFFFFFFFFu, s1, o);
    }
    if (lane == 0) {
        float* orow = out + ((size_t)b * S_ + s) * CC_;
        if (s < lengths[b]) {
            orow[0] = s0 + linb[0];
            orow[1] = s1 + linb[1];
        } else {
            orow[0] = 1.0f;
            orow[1] = 0.0f;
        }
    }
}

extern "C" void kernel_launch(void* const* d_in, const int* in_sizes, int n_in,
                              void* d_out, int out_size) {
    const int*   x       = (const int*)d_in[0];
    const int*   lengths = (const int*)d_in[1];
    const float* embW    = (const float*)d_in[2];
    const float* W_ih    = (const float*)d_in[3];
    const float* W_hh    = (const float*)d_in[4];
    const float* b_ih    = (const float*)d_in[5];
    const float* b_hh    = (const float*)d_in[6];
    const float* linW    = (const float*)d_in[7];
    const float* linb    = (const float*)d_in[8];
    float*       out     = (float*)d_out;

    static bool attr_done = false;
    if (!attr_done) {
        cudaFuncSetAttribute(lstm_persistent,
                             cudaFuncAttributeMaxDynamicSharedMemorySize, SMEM_BYTES);
        attr_done = true;
    }

    init_state<<<512, 256>>>();
    embed_gemm<<<dim3(128, 64), 256>>>(x, embW, W_ih, b_ih, b_hh);
    lstm_persistent<<<128, 256, SMEM_BYTES>>>(W_hh);
    out_proj<<<2048, 256>>>(lengths, linW, linb, out);
}

// round 8
// speedup vs baseline: 2.6180x; 1.7187x over previous
#include <cuda_runtime.h>
#include <cuda_bf16.h>
#include <cstdint>

#define B_   128
#define S_   128
#define I_   300
#define H_   1024
#define G4_  4096
#define CC_  2
#define PW_  512                   // pair-words per h row (1024 bf16 / 2)

#define WSTRIDE 528                // u32 words per W smem row (512 + 16 pad; %32==16)
#define ASTRIDE 80                 // u32 words per A-stage row (64 + 16 pad; %32==16)
#define SMEM_WORDS (32 * WSTRIDE + 2 * 128 * ASTRIDE)
#define SMEM_BYTES (SMEM_WORDS * 4)

__device__ float    d_G[(size_t)S_ * B_ * G4_];
__device__ uint32_t d_hsu[(size_t)(S_ + 1) * B_ * PW_];   // bf16-pair h, permuted
__device__ int      d_ctr;

__device__ __forceinline__ uint32_t f2tf(float x) {
    uint32_t u; asm("cvt.rna.tf32.f32 %0, %1;" : "=r"(u) : "f"(x)); return u;
}
__device__ __forceinline__ uint32_t f2tf_u(uint32_t raw) { return f2tf(__uint_as_float(raw)); }
__device__ __forceinline__ uint32_t smem_u32(const void* p) {
    uint32_t a;
    asm("{ .reg .u64 t; cvta.to.shared.u64 t, %1; cvt.u32.u64 %0, t; }" : "=r"(a) : "l"(p));
    return a;
}
__device__ __forceinline__ void mma_tf32(float c[4], const uint32_t a[4], const uint32_t b[2]) {
    asm volatile(
        "mma.sync.aligned.m16n8k8.row.col.f32.tf32.tf32.f32 "
        "{%0,%1,%2,%3}, {%4,%5,%6,%7}, {%8,%9}, {%0,%1,%2,%3};\n"
        : "+f"(c[0]), "+f"(c[1]), "+f"(c[2]), "+f"(c[3])
        : "r"(a[0]), "r"(a[1]), "r"(a[2]), "r"(a[3]), "r"(b[0]), "r"(b[1]));
}
__device__ __forceinline__ void mma_bf16(float c[4], const uint32_t a[4], const uint32_t b[2]) {
    asm volatile(
        "mma.sync.aligned.m16n8k16.row.col.f32.bf16.bf16.f32 "
        "{%0,%1,%2,%3}, {%4,%5,%6,%7}, {%8,%9}, {%0,%1,%2,%3};\n"
        : "+f"(c[0]), "+f"(c[1]), "+f"(c[2]), "+f"(c[3])
        : "r"(a[0]), "r"(a[1]), "r"(a[2]), "r"(a[3]), "r"(b[0]), "r"(b[1]));
}
__device__ __forceinline__ float sigf(float x)   { return 1.0f / (1.0f + __expf(-x)); }
__device__ __forceinline__ float tanhf_(float x) { return 2.0f / (1.0f + __expf(-2.0f * x)) - 1.0f; }
__host__ __device__ __forceinline__ int perm16(int k) {
    return (k & ~15) | ((k & 3) << 2) | ((k >> 2) & 3);
}
__device__ __forceinline__ int swz(int w, int row) {
    return w ^ ((row & 7) << 2) ^ (((w >> 5) & 1) << 2);
}
__device__ __forceinline__ void bar_arrive() {
    asm volatile("red.release.gpu.global.add.s32 [%0], 1;" :: "l"(&d_ctr) : "memory");
}
__device__ __forceinline__ int bar_poll() {
    int v;
    asm volatile("ld.acquire.gpu.global.b32 %0, [%1];" : "=r"(v) : "l"(&d_ctr) : "memory");
    return v;
}
__device__ __forceinline__ void cpa16(uint32_t dst, const void* src, int src_bytes) {
    asm volatile("cp.async.cg.shared.global [%0], [%1], 16, %2;"
                 :: "r"(dst), "l"(src), "r"(src_bytes) : "memory");
}

__global__ void init_state() {
    int idx = blockIdx.x * 256 + threadIdx.x;
    if (idx < B_ * PW_) d_hsu[idx] = 0u;   // slot 0 = h0 = 0
    if (idx == 0) d_ctr = 0;
}

// ---------------- input-path GEMM (unchanged R6, known-good) ----------------
__global__ __launch_bounds__(256) void embed_gemm(
    const int* __restrict__ x, const float* __restrict__ embW,
    const float* __restrict__ W_ih, const float* __restrict__ b_ih,
    const float* __restrict__ b_hh)
{
    __shared__ uint32_t As[2][128][20];
    __shared__ uint32_t Bs[2][64][20];
    __shared__ int toks[128];

    const int tid = threadIdx.x;
    const int s   = blockIdx.x;
    const int n0  = blockIdx.y * 64;

    if (tid < 128) toks[tid] = x[tid * S_ + s];

    const int w  = tid >> 5, lane = tid & 31;
    const int wm = w >> 1,   wn   = w & 1;
    const int gr = lane >> 2, gc  = lane & 3;
    const int mw = wm * 32,  nw   = wn * 32;

    const int arow = tid >> 1, akb = (tid & 1) * 8;
    const int brow = tid >> 2, bkb = (tid & 3) * 4;

    __syncthreads();

    const float* aptr = embW + (size_t)toks[arow] * I_;
    const float* bptr = W_ih + (size_t)(n0 + brow) * I_;

    auto stage = [&](int kt, int bi) {
        const int k0 = kt * 16;
#pragma unroll
        for (int q = 0; q < 2; q++) {
            int kq = k0 + akb + q * 4;
            int sz = (I_ - kq) * 4; sz = sz < 0 ? 0 : (sz > 16 ? 16 : sz);
            cpa16(smem_u32(&As[bi][arow][akb + q * 4]), aptr + (sz ? kq : 0), sz);
        }
        {
            int kq = k0 + bkb;
            int sz = (I_ - kq) * 4; sz = sz < 0 ? 0 : (sz > 16 ? 16 : sz);
            cpa16(smem_u32(&Bs[bi][brow][bkb]), bptr + (sz ? kq : 0), sz);
        }
        asm volatile("cp.async.commit_group;" ::: "memory");
    };

    float acc[2][4][4];
#pragma unroll
    for (int mi = 0; mi < 2; mi++)
#pragma unroll
        for (int ni = 0; ni < 4; ni++)
#pragma unroll
            for (int q = 0; q < 4; q++) acc[mi][ni][q] = 0.0f;

    stage(0, 0);

    for (int kt = 0; kt < 19; kt++) {
        const int bi = kt & 1;
        if (kt < 18) {
            stage(kt + 1, bi ^ 1);
            asm volatile("cp.async.wait_group 1;" ::: "memory");
        } else {
            asm volatile("cp.async.wait_group 0;" ::: "memory");
        }
        __syncthreads();

#pragma unroll
        for (int ks = 0; ks < 2; ks++) {
            uint32_t a[2][4], b[4][2];
#pragma unroll
            for (int mi = 0; mi < 2; mi++) {
                a[mi][0] = f2tf_u(As[bi][mw + mi * 16 + gr][ks * 8 + gc]);
                a[mi][1] = f2tf_u(As[bi][mw + mi * 16 + 8 + gr][ks * 8 + gc]);
                a[mi][2] = f2tf_u(As[bi][mw + mi * 16 + gr][ks * 8 + 4 + gc]);
                a[mi][3] = f2tf_u(As[bi][mw + mi * 16 + 8 + gr][ks * 8 + 4 + gc]);
            }
#pragma unroll
            for (int ni = 0; ni < 4; ni++) {
                b[ni][0] = f2tf_u(Bs[bi][nw + ni * 8 + gr][ks * 8 + gc]);
                b[ni][1] = f2tf_u(Bs[bi][nw + ni * 8 + gr][ks * 8 + 4 + gc]);
            }
#pragma unroll
            for (int mi = 0; mi < 2; mi++)
#pragma unroll
                for (int ni = 0; ni < 4; ni++)
                    mma_tf32(acc[mi][ni], a[mi], b[ni]);
        }
        __syncthreads();
    }

#pragma unroll
    for (int mi = 0; mi < 2; mi++) {
        const int m0 = mw + mi * 16 + gr;
#pragma unroll
        for (int ni = 0; ni < 4; ni++) {
            const int n = n0 + nw + ni * 8 + gc * 2;
            const float bias0 = b_ih[n] + b_hh[n];
            const float bias1 = b_ih[n + 1] + b_hh[n + 1];
            size_t base0 = ((size_t)s * B_ + m0) * G4_ + n;
            size_t base1 = ((size_t)s * B_ + m0 + 8) * G4_ + n;
            d_G[base0]     = acc[mi][ni][0] + bias0;
            d_G[base0 + 1] = acc[mi][ni][1] + bias1;
            d_G[base1]     = acc[mi][ni][2] + bias0;
            d_G[base1 + 1] = acc[mi][ni][3] + bias1;
        }
    }
}

// ---------------- persistent recurrence: bf16 m16n8k16 ----------------
extern __shared__ uint32_t smem_dynu[];

__device__ __forceinline__ void stage_async(uint32_t* As_buf, const uint32_t* hrow_base,
                                            int chunk, int srow, int shalf)
{
    const uint32_t* src = hrow_base + (size_t)srow * PW_ + chunk * 64 + shalf * 32;
    uint32_t* dst = As_buf + srow * ASTRIDE;
#pragma unroll
    for (int q = 0; q < 8; q++) {
        int wloc = shalf * 32 + q * 4;
        uint32_t da = smem_u32(dst + swz(wloc, srow));
        asm volatile("cp.async.cg.shared.global [%0], [%1], 16;"
                     :: "r"(da), "l"(src + q * 4) : "memory");
    }
}

__global__ void __launch_bounds__(256, 1) lstm_persistent(const float* __restrict__ W_hh)
{
    uint32_t* Ws  = smem_dynu;
    uint32_t* Ast = smem_dynu + 32 * WSTRIDE;

    const int tid = threadIdx.x;
    const int bid = blockIdx.x;
    const int c0  = bid * 8;

    const int w  = tid >> 5, lane = tid & 31;
    const int gr = lane >> 2, gc = lane & 3;
    const int mw = (w >> 1) * 32;
    const int nw = (w & 1) * 16;

    const int srow = tid >> 1, shalf = tid & 1;

    // preload W slice as bf16 pairs, permuted pair-words, swizzled
    for (int i = tid; i < 32 * PW_; i += 256) {
        int p = i >> 9, wq = i & 511;
        int gate = ((p >> 3) & 1) * 2 + (p & 1);
        int jloc = ((p >> 4) & 1) * 4 + ((p >> 1) & 3);
        int q = perm16(wq);                       // original pair index
        const float* wr = W_hh + (size_t)(gate * H_ + c0 + jloc) * H_ + 2 * q;
        __nv_bfloat162 pk = __floats2bfloat162_rn(wr[0], wr[1]);   // low = even k
        Ws[p * WSTRIDE + swz(wq, p)] = *reinterpret_cast<uint32_t*>(&pk);
    }
    __syncthreads();

    const int jloc_t = (w & 1) * 4 + gc;
    const int jglob  = c0 + jloc_t;
    const int ppos   = perm16(jglob >> 1);        // pair position in stored h
    const int phalf  = jglob & 1;

    float cReg[4] = {0.0f, 0.0f, 0.0f, 0.0f};

    for (int t = 0; t < S_; t++) {
        const uint32_t* hrow = d_hsu + (size_t)t * (B_ * PW_);

        stage_async(Ast, hrow, 0, srow, shalf);
        asm volatile("cp.async.commit_group;" ::: "memory");

        float gv[2][2][4];
        {
            const float* Gt = d_G + (size_t)t * B_ * G4_;
#pragma unroll
            for (int mi = 0; mi < 2; mi++)
#pragma unroll
                for (int rs = 0; rs < 2; rs++) {
                    int r = mw + mi * 16 + gr + rs * 8;
                    const float* Gr = Gt + (size_t)r * G4_ + jglob;
#pragma unroll
                    for (int g = 0; g < 4; g++) gv[mi][rs][g] = Gr[g * H_];
                }
        }

        float acc[2][2][4];
#pragma unroll
        for (int mi = 0; mi < 2; mi++)
#pragma unroll
            for (int ni = 0; ni < 2; ni++)
#pragma unroll
                for (int q = 0; q < 4; q++) acc[mi][ni][q] = 0.0f;

        for (int c = 0; c < 8; c++) {
            if (c < 7) {
                stage_async(Ast + ((c + 1) & 1) * (128 * ASTRIDE), hrow, c + 1, srow, shalf);
                asm volatile("cp.async.commit_group;" ::: "memory");
                asm volatile("cp.async.wait_group 1;" ::: "memory");
            } else {
                asm volatile("cp.async.wait_group 0;" ::: "memory");
            }
            __syncthreads();

            const uint32_t* Ab = Ast + (c & 1) * (128 * ASTRIDE);
#pragma unroll
            for (int gl = 0; gl < 4; gl++) {
                const int wbase = gl * 16 + gc * 4;
                uint4 av[2][2], bv[2];
#pragma unroll
                for (int mi = 0; mi < 2; mi++) {
                    const int R0 = mw + mi * 16 + gr;
                    av[mi][0] = *reinterpret_cast<const uint4*>(Ab + R0 * ASTRIDE + swz(wbase, R0));
                    av[mi][1] = *reinterpret_cast<const uint4*>(Ab + (R0 + 8) * ASTRIDE + swz(wbase, R0 + 8));
                }
                const int wfull = c * 64 + gl * 16 + gc * 4;
#pragma unroll
                for (int ni = 0; ni < 2; ni++) {
                    const int nb = nw + ni * 8 + gr;
                    bv[ni] = *reinterpret_cast<const uint4*>(Ws + nb * WSTRIDE + swz(wfull, nb));
                }
                {   // first 16 k of this 32-k group
                    uint32_t b0[2] = {bv[0].x, bv[0].y};
                    uint32_t b1[2] = {bv[1].x, bv[1].y};
#pragma unroll
                    for (int mi = 0; mi < 2; mi++) {
                        uint32_t a[4] = {av[mi][0].x, av[mi][1].x, av[mi][0].y, av[mi][1].y};
                        mma_bf16(acc[mi][0], a, b0);
                        mma_bf16(acc[mi][1], a, b1);
                    }
                }
                {   // second 16 k
                    uint32_t b0[2] = {bv[0].z, bv[0].w};
                    uint32_t b1[2] = {bv[1].z, bv[1].w};
#pragma unroll
                    for (int mi = 0; mi < 2; mi++) {
                        uint32_t a[4] = {av[mi][0].z, av[mi][1].z, av[mi][0].w, av[mi][1].w};
                        mma_bf16(acc[mi][0], a, b0);
                        mma_bf16(acc[mi][1], a, b1);
                    }
                }
            }
            __syncthreads();
        }

        // epilogue: add G, cell update, write bf16 h
        __nv_bfloat16* hout = reinterpret_cast<__nv_bfloat16*>(
            d_hsu + (size_t)(t + 1) * (B_ * PW_));
#pragma unroll
        for (int mi = 0; mi < 2; mi++)
#pragma unroll
            for (int rs = 0; rs < 2; rs++) {
                const int r = mw + mi * 16 + gr + rs * 8;
                const float ig = acc[mi][0][rs * 2]     + gv[mi][rs][0];
                const float fg = acc[mi][0][rs * 2 + 1] + gv[mi][rs][1];
                const float gg = acc[mi][1][rs * 2]     + gv[mi][rs][2];
                const float og = acc[mi][1][rs * 2 + 1] + gv[mi][rs][3];
                const int ci = mi * 2 + rs;
                const float cn = sigf(fg) * cReg[ci] + sigf(ig) * tanhf_(gg);
                cReg[ci] = cn;
                const float h = sigf(og) * tanhf_(cn);
                hout[(size_t)r * (2 * PW_) + 2 * ppos + phalf] = __float2bfloat16_rn(h);
            }

        __syncthreads();
        if (tid == 0) {
            bar_arrive();
            const int tgt = 128 * (t + 1);
            while (bar_poll() < tgt) { __nanosleep(40); }
        }
        __syncthreads();
    }
}

// ---------------- output projection + mask ----------------
__global__ __launch_bounds__(256) void out_proj(
    const int* __restrict__ lengths, const float* __restrict__ linW,
    const float* __restrict__ linb, float* __restrict__ out)
{
    const int gw   = (blockIdx.x * 256 + threadIdx.x) >> 5;
    const int lane = threadIdx.x & 31;
    const int b = gw >> 7;
    const int s = gw & 127;

    const uint32_t* __restrict__ h = d_hsu + ((size_t)(s + 1) * B_ + b) * PW_;
    float s0 = 0.0f, s1 = 0.0f;
#pragma unroll 4
    for (int p = lane; p < PW_; p += 32) {
        uint32_t u = h[p];
        __nv_bfloat162 pk = *reinterpret_cast<__nv_bfloat162*>(&u);
        const int k2 = 2 * perm16(p);
        const float h0 = __bfloat162float(pk.x), h1 = __bfloat162float(pk.y);
        s0 += h0 * linW[k2] + h1 * linW[k2 + 1];
        s1 += h0 * linW[H_ + k2] + h1 * linW[H_ + k2 + 1];
    }
#pragma unroll
    for (int o = 16; o > 0; o >>= 1) {
        s0 += __shfl_xor_sync(0xFFFFFFFFu, s0, o);
        s1 += __shfl_xor_sync(0xFFFFFFFFu, s1, o);
    }
    if (lane == 0) {
        float* orow = out + ((size_t)b * S_ + s) * CC_;
        if (s < lengths[b]) {
            orow[0] = s0 + linb[0];
            orow[1] = s1 + linb[1];
        } else {
            orow[0] = 1.0f;
            orow[1] = 0.0f;
        }
    }
}

extern "C" void kernel_launch(void* const* d_in, const int* in_sizes, int n_in,
                              void* d_out, int out_size) {
    const int*   x       = (const int*)d_in[0];
    const int*   lengths = (const int*)d_in[1];
    const float* embW    = (const float*)d_in[2];
    const float* W_ih    = (const float*)d_in[3];
    const float* W_hh    = (const float*)d_in[4];
    const float* b_ih    = (const float*)d_in[5];
    const float* b_hh    = (const float*)d_in[6];
    const float* linW    = (const float*)d_in[7];
    const float* linb    = (const float*)d_in[8];
    float*       out     = (float*)d_out;

    static bool attr_done = false;
    if (!attr_done) {
        cudaFuncSetAttribute(lstm_persistent,
                             cudaFuncAttributeMaxDynamicSharedMemorySize, SMEM_BYTES);
        attr_done = true;
    }

    init_state<<<512, 256>>>();
    embed_gemm<<<dim3(128, 64), 256>>>(x, embW, W_ih, b_ih, b_hh);
    lstm_persistent<<<128, 256, SMEM_BYTES>>>(W_hh);
    out_proj<<<2048, 256>>>(lengths, linW, linb, out);
}